// round 1
// baseline (speedup 1.0000x reference)
#include <cuda_runtime.h>
#include <cuda_bf16.h>

// EdgeToVertex: tril(x) convolved with a 257x257 "plus" kernel, stride (256,1),
// SAME padding -> out [512, 1, 256, 1].
//
// Exact algebraic reduction:
//   out[b,w] = sum_{r=w..255} x[b,r,w]          (column suffix sum, tril)
//            + S                                 (S = sum_{c=0..128} x[b,128,c])
//            - 2*x[b,128,w]            if w <= 128
//            - prefix128(w-129)        if w >= 129   (prefix128(k)=sum_{c=0..k} x[b,128,c])
//
// One CTA per batch image, one thread per output column. Loads only the lower
// triangle (row-coalesced, warp-uniform loop start), ~67 MB total -> HBM-bound.

#define NN 256
#define NB 512

__global__ __launch_bounds__(256) void etv_kernel(const float* __restrict__ x,
                                                  float* __restrict__ out) {
    const int b = blockIdx.x;
    const int w = threadIdx.x;                       // output column, 0..255
    const float* __restrict__ X = x + (size_t)b * (NN * NN);

    __shared__ float sdata[NN];

    float acc = 0.0f;
    const int r0 = w & ~31;                          // warp-uniform start row

    // Boundary 32 rows: predicated per-lane (triangle edge), still coalesced.
    #pragma unroll
    for (int i = 0; i < 32; ++i) {
        const int r = r0 + i;                        // r0 <= 224, so r <= 255
        if (r >= w) acc += X[r * NN + w];
    }
    // Remaining rows: all lanes active, fully coalesced 128B per warp per row.
    #pragma unroll 8
    for (int r = r0 + 32; r < NN; ++r) {
        acc += X[r * NN + w];
    }

    // Stage row 128 (tril: only cols 0..128 are nonzero) and scan it.
    const float myv = (w <= 128) ? X[128 * NN + w] : 0.0f;
    sdata[w] = myv;
    __syncthreads();

    // Hillis-Steele inclusive prefix scan over 256 elements.
    #pragma unroll
    for (int off = 1; off < NN; off <<= 1) {
        float t = (w >= off) ? sdata[w - off] : 0.0f;
        __syncthreads();
        sdata[w] += t;
        __syncthreads();
    }

    const float S = sdata[128];                      // sum of row-128 cols 0..128
    float res;
    if (w <= 128) {
        // colsum excludes r=128 (-myv) and rowsum excludes c=w (-myv)
        res = acc + S - 2.0f * myv;
    } else {
        // rowsum window is cols [w-128 .. 128] = S - prefix(w-129)
        res = acc + S - sdata[w - 129];
    }
    out[b * NN + w] = res;
}

extern "C" void kernel_launch(void* const* d_in, const int* in_sizes, int n_in,
                              void* d_out, int out_size) {
    // Inputs: x [512,256,256,1] f32 and scalar n. Pick x by element count
    // to be robust to metadata ordering.
    const float* x = (const float*)d_in[0];
    if (n_in > 1 && in_sizes[0] != NB * NN * NN) {
        for (int i = 0; i < n_in; ++i) {
            if (in_sizes[i] == NB * NN * NN) { x = (const float*)d_in[i]; break; }
        }
    }
    float* out = (float*)d_out;
    etv_kernel<<<NB, NN>>>(x, out);
}